// round 1
// baseline (speedup 1.0000x reference)
#include <cuda_runtime.h>
#include <cuda_bf16.h>
#include <cstdint>

#define N_ROWS 8192
#define DIM    1024
#define MARGIN 0.3f

// ---------------- device scratch (no allocations allowed) ----------------
__device__ __nv_bfloat16 g_xn[N_ROWS * DIM];   // 16 MB
__device__ __nv_bfloat16 g_yn[N_ROWS * DIM];   // 16 MB
__device__ float g_rowsum[N_ROWS];             // sum_j exp(S[i,j]) incl diag
__device__ float g_colsum[N_ROWS];             // sum_i exp(S[i,j]) incl diag
__device__ float g_diag[N_ROWS];               // S[i,i] in fp32

// ---------------- kernel 1: normalize rows, emit bf16, zero accumulators ----
__global__ void __launch_bounds__(256) normalize_kernel(const float* __restrict__ x,
                                                        const float* __restrict__ y) {
    int bid = blockIdx.x;
    int row = bid & (N_ROWS - 1);
    bool isx = bid < N_ROWS;
    const float* src = (isx ? x : y) + (size_t)row * DIM;
    __nv_bfloat16* dst = (isx ? g_xn : g_yn) + (size_t)row * DIM;

    if (threadIdx.x == 0 && isx) {
        g_rowsum[row] = 0.0f;
        g_colsum[row] = 0.0f;
    }

    // 1024 floats = 256 float4, exactly one per thread
    const float4* s4 = (const float4*)src;
    float4 v = s4[threadIdx.x];
    float ss = v.x * v.x + v.y * v.y + v.z * v.z + v.w * v.w;

    // block reduce
    #pragma unroll
    for (int o = 16; o > 0; o >>= 1) ss += __shfl_xor_sync(0xffffffffu, ss, o);
    __shared__ float sw[8];
    int warp = threadIdx.x >> 5, lane = threadIdx.x & 31;
    if (lane == 0) sw[warp] = ss;
    __syncthreads();
    float tot = 0.0f;
    #pragma unroll
    for (int w = 0; w < 8; w++) tot += sw[w];

    float scale = 1.0f / fmaxf(sqrtf(tot), 1e-8f);
    __nv_bfloat162* d2 = (__nv_bfloat162*)dst;
    d2[2 * threadIdx.x + 0] = __floats2bfloat162_rn(v.x * scale, v.y * scale);
    d2[2 * threadIdx.x + 1] = __floats2bfloat162_rn(v.z * scale, v.w * scale);
}

// ---------------- kernel 2: fp32 diagonal from bf16 normalized vectors ------
__global__ void __launch_bounds__(256) diag_kernel() {
    int row = blockIdx.x;
    const __nv_bfloat162* a = (const __nv_bfloat162*)(g_xn + (size_t)row * DIM);
    const __nv_bfloat162* b = (const __nv_bfloat162*)(g_yn + (size_t)row * DIM);
    float s = 0.0f;
    // 512 bf16x2 pairs, 2 per thread
    #pragma unroll
    for (int i = 0; i < 2; i++) {
        int idx = threadIdx.x + i * 256;
        float2 fa = __bfloat1622float2(a[idx]);
        float2 fb = __bfloat1622float2(b[idx]);
        s += fa.x * fb.x + fa.y * fb.y;
    }
    #pragma unroll
    for (int o = 16; o > 0; o >>= 1) s += __shfl_xor_sync(0xffffffffu, s, o);
    __shared__ float sw[8];
    int warp = threadIdx.x >> 5, lane = threadIdx.x & 31;
    if (lane == 0) sw[warp] = s;
    __syncthreads();
    if (threadIdx.x == 0) {
        float tot = 0.0f;
        #pragma unroll
        for (int w = 0; w < 8; w++) tot += sw[w];
        g_diag[row] = tot;
    }
}

// ---------------- kernel 3: fused GEMM + exp + row/col reductions -----------
// S = xn @ yn^T ; BM=BN=128, BK=32 ; 8 warps, each computes 64x32 via
// mma.sync.aligned.m16n8k16.row.col.f32.bf16.bf16.f32
#define BM 128
#define BN 128
#define BK 32
#define SPAD 40   // padded smem row stride (elements) -> conflict-free frag loads

__device__ __forceinline__ void mma_bf16(float* c, const uint32_t* a, const uint32_t* b) {
    asm volatile(
        "mma.sync.aligned.m16n8k16.row.col.f32.bf16.bf16.f32 "
        "{%0,%1,%2,%3}, {%4,%5,%6,%7}, {%8,%9}, {%0,%1,%2,%3};\n"
        : "+f"(c[0]), "+f"(c[1]), "+f"(c[2]), "+f"(c[3])
        : "r"(a[0]), "r"(a[1]), "r"(a[2]), "r"(a[3]), "r"(b[0]), "r"(b[1]));
}

__global__ void __launch_bounds__(256) gemm_loss_kernel() {
    __shared__ __align__(16) __nv_bfloat16 As[BM * SPAD];
    __shared__ __align__(16) __nv_bfloat16 Bs[BN * SPAD];

    const int bm = blockIdx.y, bn = blockIdx.x;
    const int tid = threadIdx.x;
    const int lane = tid & 31, warp = tid >> 5;
    const int wm = (warp & 1) * 64;   // warp m offset within block tile
    const int wn = (warp >> 1) * 32;  // warp n offset within block tile
    const int g = lane >> 2;          // groupID (0..7)
    const int q = lane & 3;           // quad   (0..3)

    float acc[4][4][4];
    #pragma unroll
    for (int mi = 0; mi < 4; mi++)
        #pragma unroll
        for (int ni = 0; ni < 4; ni++)
            #pragma unroll
            for (int v = 0; v < 4; v++) acc[mi][ni][v] = 0.0f;

    const __nv_bfloat16* Ag = g_xn + (size_t)(bm * BM) * DIM;
    const __nv_bfloat16* Bg = g_yn + (size_t)(bn * BN) * DIM;

    const int lr = tid >> 2;        // 0..63 (row within half-tile)
    const int lc = (tid & 3) * 8;   // 0,8,16,24

    for (int kt = 0; kt < DIM; kt += BK) {
        // global -> shared (single buffered)
        #pragma unroll
        for (int h = 0; h < 2; h++) {
            int r = lr + h * 64;
            uint4 va = *(const uint4*)(Ag + (size_t)r * DIM + kt + lc);
            uint4 vb = *(const uint4*)(Bg + (size_t)r * DIM + kt + lc);
            *(uint4*)(As + r * SPAD + lc) = va;
            *(uint4*)(Bs + r * SPAD + lc) = vb;
        }
        __syncthreads();

        #pragma unroll
        for (int s = 0; s < 2; s++) {
            const int kk = s * 16;
            uint32_t af[4][4], bf[4][2];
            #pragma unroll
            for (int mi = 0; mi < 4; mi++) {
                const __nv_bfloat16* base = As + (wm + mi * 16 + g) * SPAD + kk + q * 2;
                af[mi][0] = *(const uint32_t*)(base);
                af[mi][1] = *(const uint32_t*)(base + 8 * SPAD);
                af[mi][2] = *(const uint32_t*)(base + 8);
                af[mi][3] = *(const uint32_t*)(base + 8 * SPAD + 8);
            }
            #pragma unroll
            for (int ni = 0; ni < 4; ni++) {
                const __nv_bfloat16* base = Bs + (wn + ni * 8 + g) * SPAD + kk + q * 2;
                bf[ni][0] = *(const uint32_t*)(base);
                bf[ni][1] = *(const uint32_t*)(base + 8);
            }
            #pragma unroll
            for (int mi = 0; mi < 4; mi++)
                #pragma unroll
                for (int ni = 0; ni < 4; ni++)
                    mma_bf16(acc[mi][ni], af[mi], bf[ni]);
        }
        __syncthreads();
    }

    // ---------------- epilogue: exp, then row/col partial sums ----------------
    #pragma unroll
    for (int mi = 0; mi < 4; mi++)
        #pragma unroll
        for (int ni = 0; ni < 4; ni++)
            #pragma unroll
            for (int v = 0; v < 4; v++) acc[mi][ni][v] = __expf(acc[mi][ni][v]);

    // row sums: C rows = g (+8). Columns spread over quad (q) and ni.
    #pragma unroll
    for (int mi = 0; mi < 4; mi++) {
        #pragma unroll
        for (int h = 0; h < 2; h++) {      // h=0 -> row g, h=1 -> row g+8
            float p = 0.0f;
            #pragma unroll
            for (int ni = 0; ni < 4; ni++) p += acc[mi][ni][2 * h] + acc[mi][ni][2 * h + 1];
            p += __shfl_xor_sync(0xffffffffu, p, 1);
            p += __shfl_xor_sync(0xffffffffu, p, 2);
            if (q == 0)
                atomicAdd(&g_rowsum[bm * BM + wm + mi * 16 + g + h * 8], p);
        }
    }
    // col sums: C cols = q*2 + h. Rows spread over g and mi.
    #pragma unroll
    for (int ni = 0; ni < 4; ni++) {
        #pragma unroll
        for (int h = 0; h < 2; h++) {      // col = q*2+h within the 8-wide tile
            float p = 0.0f;
            #pragma unroll
            for (int mi = 0; mi < 4; mi++) p += acc[mi][ni][h] + acc[mi][ni][h + 2];
            p += __shfl_xor_sync(0xffffffffu, p, 4);
            p += __shfl_xor_sync(0xffffffffu, p, 8);
            p += __shfl_xor_sync(0xffffffffu, p, 16);
            if (g == 0)
                atomicAdd(&g_colsum[bn * BN + wn + ni * 8 + q * 2 + h], p);
        }
    }
}

// ---------------- kernel 4: final loss ---------------------------------------
__global__ void __launch_bounds__(256) final_kernel(float* __restrict__ out) {
    double s = 0.0;
    for (int i = threadIdx.x; i < N_ROWS; i += 256) {
        float d = g_diag[i];
        float ed = expf(d);
        float m1 = expf(d - MARGIN);
        float negr = g_rowsum[i] - ed;
        float negc = g_colsum[i] - ed;
        // -log(m1/(m1+neg)) = log1p(neg/m1)
        s += (double)log1pf(negr / m1) + (double)log1pf(negc / m1);
    }
    #pragma unroll
    for (int o = 16; o > 0; o >>= 1) s += __shfl_xor_sync(0xffffffffu, s, o);
    __shared__ double sw[8];
    int warp = threadIdx.x >> 5, lane = threadIdx.x & 31;
    if (lane == 0) sw[warp] = s;
    __syncthreads();
    if (threadIdx.x == 0) {
        double t = 0.0;
        #pragma unroll
        for (int w = 0; w < 8; w++) t += sw[w];
        out[0] = (float)(t / (double)N_ROWS);
    }
}

// ---------------- launch --------------------------------------------------
extern "C" void kernel_launch(void* const* d_in, const int* in_sizes, int n_in,
                              void* d_out, int out_size) {
    const float* x = (const float*)d_in[0];
    const float* y = (const float*)d_in[1];
    float* out = (float*)d_out;

    normalize_kernel<<<2 * N_ROWS, 256>>>(x, y);
    diag_kernel<<<N_ROWS, 256>>>();
    dim3 grid(N_ROWS / BN, N_ROWS / BM);
    gemm_loss_kernel<<<grid, 256>>>();
    final_kernel<<<1, 256>>>(out);
}